// round 4
// baseline (speedup 1.0000x reference)
#include <cuda_runtime.h>
#include <cstddef>

// Problem constants (fixed by the reference)
constexpr int CB   = 64;    // batch
constexpr int CP   = 2048;  // points
constexpr int CK   = 16;    // neighbors
constexpr int CDIM = 3;
constexpr int CNC  = 16;    // rbf centers
constexpr int CSFD = 64;    // spatial feature dim
constexpr int COUT = 64;    // output features

constexpr int PTS     = 32;   // points per block
constexpr int THREADS = 256;  // 8 warps, 4 points per warp
constexpr int FPP     = CK * CDIM;  // 48 floats of features per point

__global__ __launch_bounds__(THREADS, 4)
void rbfn_fused_kernel(const float* __restrict__ features,
                       const float* __restrict__ spatial,
                       const float* __restrict__ centers,
                       const float* __restrict__ rbfw,
                       const float* __restrict__ w,
                       float* __restrict__ out)
{
    __shared__ float w_sh[CSFD * COUT];     // 16 KB : w[b] slice
    __shared__ float rbfn_sh[CNC * CSFD];   // 4 KB
    __shared__ float cen_sh[CDIM * CNC];    // 192 B : centers (dim-major)
    __shared__ float x_sh[PTS * CSFD];      // 8 KB : fused x = fl * sp_sum
    __shared__ float feat_sh[PTS * FPP];    // 6 KB : staged features

    const int tid = threadIdx.x;
    const int b   = blockIdx.y;
    const int p0  = blockIdx.x * PTS;

    // ---- stage per-batch weight slice + constants + features into smem ----
    {
        const float4* wsrc = reinterpret_cast<const float4*>(w + (size_t)b * CSFD * COUT);
        float4* wdst = reinterpret_cast<float4*>(w_sh);
        #pragma unroll
        for (int i = 0; i < (CSFD * COUT / 4) / THREADS; i++)   // 4 iters
            wdst[tid + i * THREADS] = wsrc[tid + i * THREADS];

        const float4* rsrc = reinterpret_cast<const float4*>(rbfw);
        reinterpret_cast<float4*>(rbfn_sh)[tid & 255] = rsrc[tid & 255]; // 256 float4

        // features for this block's 32 points: 1536 floats = 384 float4, coalesced
        const float4* fsrc = reinterpret_cast<const float4*>(
            features + ((size_t)b * CP + p0) * FPP);
        float4* fdst = reinterpret_cast<float4*>(feat_sh);
        for (int i = tid; i < PTS * FPP / 4; i += THREADS)
            fdst[i] = fsrc[i];

        if (tid < CDIM * CNC) cen_sh[tid] = centers[tid];
    }
    __syncthreads();

    const int warp = tid >> 5;
    const int lane = tid & 31;
    const int cg   = lane & 15;   // column group (s = 4*cg..4*cg+3) AND center id
    const int half = lane >> 4;   // which half of the K rows this lane covers

    // ---- Phase 1a: spatial sums for 4 points, interleaved for MLP ----
    float sx[4], sy[4], sz[4], sw[4];
    #pragma unroll
    for (int j = 0; j < 4; j++) { sx[j] = sy[j] = sz[j] = sw[j] = 0.f; }

    const float4* spv = reinterpret_cast<const float4*>(
        spatial + ((size_t)b * CP + p0 + warp * 4) * (CK * CSFD));
    #pragma unroll
    for (int i = 0; i < 8; i++) {
        #pragma unroll
        for (int j = 0; j < 4; j++) {
            float4 v = spv[j * 256 + i * 32 + lane];
            sx[j] += v.x; sy[j] += v.y; sz[j] += v.z; sw[j] += v.w;
        }
    }
    #pragma unroll
    for (int j = 0; j < 4; j++) {
        sx[j] += __shfl_xor_sync(0xffffffffu, sx[j], 16);
        sy[j] += __shfl_xor_sync(0xffffffffu, sy[j], 16);
        sz[j] += __shfl_xor_sync(0xffffffffu, sz[j], 16);
        sw[j] += __shfl_xor_sync(0xffffffffu, sw[j], 16);
    }

    // ---- Phase 1b: RBF sums (lane -> center cg, covers 8 k's of its half) ----
    const float c0 = cen_sh[0 * CNC + cg];
    const float c1 = cen_sh[1 * CNC + cg];
    const float c2 = cen_sh[2 * CNC + cg];

    float racc[4] = {0.f, 0.f, 0.f, 0.f};
    #pragma unroll
    for (int i = 0; i < 8; i++) {
        const int k = 2 * i + half;
        #pragma unroll
        for (int j = 0; j < 4; j++) {
            const float* fb = feat_sh + (warp * 4 + j) * FPP + k * 3;
            float d0 = fb[0] - c0;
            float d1 = fb[1] - c1;
            float d2 = fb[2] - c2;
            float dn2 = d0 * d0 + d1 * d1 + d2 * d2;
            racc[j] += __expf(dn2 * -12.5f);   // 1/0.08 = 12.5
        }
    }
    #pragma unroll
    for (int j = 0; j < 4; j++)
        racc[j] += __shfl_xor_sync(0xffffffffu, racc[j], 16);
    // lane c (and c+16) now holds rbf_sum for center c

    // ---- Phase 1c: feature layer (s = 4*cg..4*cg+3) fused with spatial ----
    #pragma unroll
    for (int j = 0; j < 4; j++) {
        float flx = 0.f, fly = 0.f, flz = 0.f, flw = 0.f;
        #pragma unroll
        for (int c = 0; c < CNC; c++) {
            float rv  = __shfl_sync(0xffffffffu, racc[j], c);
            float4 wv = reinterpret_cast<const float4*>(rbfn_sh)[c * 16 + cg];
            flx += rv * wv.x; fly += rv * wv.y; flz += rv * wv.z; flw += rv * wv.w;
        }
        if (half == 0) {
            float4 xv;
            xv.x = flx * sx[j]; xv.y = fly * sy[j];
            xv.z = flz * sz[j]; xv.w = flw * sw[j];
            reinterpret_cast<float4*>(x_sh)[(warp * 4 + j) * 16 + cg] = xv;
        }
    }
    __syncthreads();

    // ---- Phase 2: out[pt][o] = sum_s x[pt][s] * w_sh[s][o] ----
    const int o  = tid & 63;
    const int pg = tid >> 6;

    float acc[8];
    #pragma unroll
    for (int jj = 0; jj < 8; jj++) acc[jj] = 0.f;

    #pragma unroll
    for (int sq = 0; sq < CSFD / 4; sq++) {
        float w0 = w_sh[(4 * sq + 0) * COUT + o];
        float w1 = w_sh[(4 * sq + 1) * COUT + o];
        float w2 = w_sh[(4 * sq + 2) * COUT + o];
        float w3 = w_sh[(4 * sq + 3) * COUT + o];
        #pragma unroll
        for (int jj = 0; jj < 8; jj++) {
            float4 xv = reinterpret_cast<const float4*>(x_sh)[(pg * 8 + jj) * 16 + sq];
            acc[jj] += xv.x * w0 + xv.y * w1 + xv.z * w2 + xv.w * w3;
        }
    }

    float* ob = out + ((size_t)b * CP + p0) * COUT;
    #pragma unroll
    for (int jj = 0; jj < 8; jj++)
        ob[(size_t)(pg * 8 + jj) * COUT + o] = acc[jj];
}

extern "C" void kernel_launch(void* const* d_in, const int* in_sizes, int n_in,
                              void* d_out, int out_size)
{
    const float* features = (const float*)d_in[0];
    const float* spatial  = (const float*)d_in[1];
    const float* centers  = (const float*)d_in[2];
    const float* rbfw     = (const float*)d_in[3];
    const float* w        = (const float*)d_in[4];
    // d_in[5] is K (=16), fixed at compile time
    float* out = (float*)d_out;

    dim3 grid(CP / PTS, CB);
    rbfn_fused_kernel<<<grid, THREADS>>>(features, spatial, centers, rbfw, w, out);
}

// round 5
// speedup vs baseline: 1.2404x; 1.2404x over previous
#include <cuda_runtime.h>
#include <cstddef>

// Problem constants (fixed by the reference)
constexpr int CB   = 64;    // batch
constexpr int CP   = 2048;  // points
constexpr int CK   = 16;    // neighbors
constexpr int CDIM = 3;
constexpr int CNC  = 16;    // rbf centers
constexpr int CSFD = 64;    // spatial feature dim
constexpr int COUT = 64;    // output features

constexpr int PTS     = 16;   // points per block (2 per warp)
constexpr int THREADS = 256;  // 8 warps
constexpr int FPP     = CK * CDIM;  // 48 floats of features per point

__global__ __launch_bounds__(THREADS, 4)
void rbfn_fused_kernel(const float* __restrict__ features,
                       const float* __restrict__ spatial,
                       const float* __restrict__ centers,
                       const float* __restrict__ rbfw,
                       const float* __restrict__ w,
                       float* __restrict__ out)
{
    __shared__ float w_sh[CSFD * COUT];     // 16 KB : w[b] slice
    __shared__ float rbfn_sh[CNC * CSFD];   // 4 KB
    __shared__ float cen_sh[CDIM * CNC];    // 192 B
    __shared__ float x_sh[PTS * CSFD];      // 4 KB : fused x = fl * sp_sum
    __shared__ float feat_sh[PTS * FPP];    // 3 KB : staged features

    const int tid = threadIdx.x;
    const int b   = blockIdx.y;
    const int p0  = blockIdx.x * PTS;

    // ---- stage per-batch weight slice + constants + features into smem ----
    {
        const float4* wsrc = reinterpret_cast<const float4*>(w + (size_t)b * CSFD * COUT);
        float4* wdst = reinterpret_cast<float4*>(w_sh);
        #pragma unroll
        for (int i = 0; i < (CSFD * COUT / 4) / THREADS; i++)   // 4 iters
            wdst[tid + i * THREADS] = wsrc[tid + i * THREADS];

        reinterpret_cast<float4*>(rbfn_sh)[tid] =
            reinterpret_cast<const float4*>(rbfw)[tid];   // 256 float4 exactly

        // features for this block's 16 points: 768 floats = 192 float4
        const float4* fsrc = reinterpret_cast<const float4*>(
            features + ((size_t)b * CP + p0) * FPP);
        if (tid < PTS * FPP / 4)
            reinterpret_cast<float4*>(feat_sh)[tid] = fsrc[tid];

        if (tid < CDIM * CNC) cen_sh[tid] = centers[tid];
    }
    __syncthreads();

    const int warp = tid >> 5;
    const int lane = tid & 31;
    const int cg   = lane & 15;   // column group (s = 4*cg..4*cg+3) AND center id
    const int half = lane >> 4;   // which half of the K rows this lane covers

    // ---- Phase 1a: spatial sums for 2 points, interleaved for MLP ----
    float sx[2], sy[2], sz[2], sw[2];
    #pragma unroll
    for (int j = 0; j < 2; j++) { sx[j] = sy[j] = sz[j] = sw[j] = 0.f; }

    const float4* spv = reinterpret_cast<const float4*>(
        spatial + ((size_t)b * CP + p0 + warp * 2) * (CK * CSFD));
    #pragma unroll
    for (int i = 0; i < 8; i++) {
        #pragma unroll
        for (int j = 0; j < 2; j++) {
            float4 v = spv[j * 256 + i * 32 + lane];
            sx[j] += v.x; sy[j] += v.y; sz[j] += v.z; sw[j] += v.w;
        }
    }
    #pragma unroll
    for (int j = 0; j < 2; j++) {
        sx[j] += __shfl_xor_sync(0xffffffffu, sx[j], 16);
        sy[j] += __shfl_xor_sync(0xffffffffu, sy[j], 16);
        sz[j] += __shfl_xor_sync(0xffffffffu, sz[j], 16);
        sw[j] += __shfl_xor_sync(0xffffffffu, sw[j], 16);
    }

    // ---- Phase 1b: RBF sums (lane -> center cg, 8 k's of its half) ----
    const float c0 = cen_sh[0 * CNC + cg];
    const float c1 = cen_sh[1 * CNC + cg];
    const float c2 = cen_sh[2 * CNC + cg];

    float racc[2] = {0.f, 0.f};
    #pragma unroll
    for (int i = 0; i < 8; i++) {
        const int k = 2 * i + half;
        #pragma unroll
        for (int j = 0; j < 2; j++) {
            const float* fb = feat_sh + (warp * 2 + j) * FPP + k * 3;
            float d0 = fb[0] - c0;
            float d1 = fb[1] - c1;
            float d2 = fb[2] - c2;
            float dn2 = d0 * d0 + d1 * d1 + d2 * d2;
            racc[j] += __expf(dn2 * -12.5f);   // 1/0.08 = 12.5
        }
    }
    #pragma unroll
    for (int j = 0; j < 2; j++)
        racc[j] += __shfl_xor_sync(0xffffffffu, racc[j], 16);
    // lane c (and c+16) now holds rbf_sum for center c

    // ---- Phase 1c: feature layer (s = 4*cg..4*cg+3) fused with spatial ----
    #pragma unroll
    for (int j = 0; j < 2; j++) {
        float flx = 0.f, fly = 0.f, flz = 0.f, flw = 0.f;
        #pragma unroll
        for (int c = 0; c < CNC; c++) {
            float rv  = __shfl_sync(0xffffffffu, racc[j], c);
            float4 wv = reinterpret_cast<const float4*>(rbfn_sh)[c * 16 + cg];
            flx += rv * wv.x; fly += rv * wv.y; flz += rv * wv.z; flw += rv * wv.w;
        }
        if (half == 0) {
            float4 xv;
            xv.x = flx * sx[j]; xv.y = fly * sy[j];
            xv.z = flz * sz[j]; xv.w = flw * sw[j];
            reinterpret_cast<float4*>(x_sh)[(warp * 2 + j) * 16 + cg] = xv;
        }
    }
    __syncthreads();

    // ---- Phase 2: out[pt][o] = sum_s x[pt][s] * w_sh[s][o] ----
    // thread -> (o = tid&63, point group pg = tid>>6 handling 4 points)
    const int o  = tid & 63;
    const int pg = tid >> 6;

    float acc[4];
    #pragma unroll
    for (int jj = 0; jj < 4; jj++) acc[jj] = 0.f;

    #pragma unroll
    for (int sq = 0; sq < CSFD / 4; sq++) {
        float w0 = w_sh[(4 * sq + 0) * COUT + o];
        float w1 = w_sh[(4 * sq + 1) * COUT + o];
        float w2 = w_sh[(4 * sq + 2) * COUT + o];
        float w3 = w_sh[(4 * sq + 3) * COUT + o];
        #pragma unroll
        for (int jj = 0; jj < 4; jj++) {
            // warp-uniform address -> smem broadcast
            float4 xv = reinterpret_cast<const float4*>(x_sh)[(pg * 4 + jj) * 16 + sq];
            acc[jj] += xv.x * w0 + xv.y * w1 + xv.z * w2 + xv.w * w3;
        }
    }

    float* ob = out + ((size_t)b * CP + p0) * COUT;
    #pragma unroll
    for (int jj = 0; jj < 4; jj++)
        ob[(size_t)(pg * 4 + jj) * COUT + o] = acc[jj];
}

extern "C" void kernel_launch(void* const* d_in, const int* in_sizes, int n_in,
                              void* d_out, int out_size)
{
    const float* features = (const float*)d_in[0];
    const float* spatial  = (const float*)d_in[1];
    const float* centers  = (const float*)d_in[2];
    const float* rbfw     = (const float*)d_in[3];
    const float* w        = (const float*)d_in[4];
    // d_in[5] is K (=16), fixed at compile time
    float* out = (float*)d_out;

    dim3 grid(CP / PTS, CB);
    rbfn_fused_kernel<<<grid, THREADS>>>(features, spatial, centers, rbfw, w, out);
}